// round 11
// baseline (speedup 1.0000x reference)
#include <cuda_runtime.h>
#include <cuda_bf16.h>

// 3x3 high-pass stencil: y = |0.125*(hs_top+hs_mid+hs_bot) - 1.125*center| + 1e-5
// x: (8,32,512,512) fp32, zero-padded SAME. Register-rolling, smem-free.
// Split: interior kernel (row strips 1..14, unguarded loads, prefetch d=3)
//        boundary kernel (strips 0 and 15, guarded loads, prefetch d=2).

#define W 512
#define H 512
#define ROWS 32
#define TW 128

struct Row {
    float4 v;   // lane's 4 columns
    float  e;   // strip-edge neighbor: left on lane 0, right on lane 31
};

// ---- guarded row load (boundary strips) ----
__device__ __forceinline__ Row load_row_g(const float* __restrict__ xp, int rr,
                                          int c0, int col, int lane) {
    Row o;
    o.e = 0.f;
    if ((unsigned)rr < H) {
        o.v = *reinterpret_cast<const float4*>(xp + rr * W + col);
        if (lane == 0) {
            if (c0 > 0) o.e = xp[rr * W + (c0 - 1)];
        } else if (lane == 31) {
            if (c0 + TW < W) o.e = xp[rr * W + (c0 + TW)];
        }
    } else {
        o.v = make_float4(0.f, 0.f, 0.f, 0.f);
    }
    return o;
}

// ---- unguarded row load (interior strips: 0 < rr < H always) ----
__device__ __forceinline__ Row load_row_u(const float* __restrict__ xp, int rr,
                                          int c0, int col, int lane) {
    Row o;
    o.e = 0.f;
    o.v = *reinterpret_cast<const float4*>(xp + rr * W + col);
    if (lane == 0) {
        if (c0 > 0) o.e = xp[rr * W + (c0 - 1)];
    } else if (lane == 31) {
        if (c0 + TW < W) o.e = xp[rr * W + (c0 + TW)];
    }
    return o;
}

__device__ __forceinline__ float4 hsum(const Row& rw, int lane) {
    float l = __shfl_up_sync(0xffffffffu, rw.v.w, 1);
    if (lane == 0) l = rw.e;
    float r = __shfl_down_sync(0xffffffffu, rw.v.x, 1);
    if (lane == 31) r = rw.e;
    float4 h;
    h.x = l      + rw.v.x + rw.v.y;
    h.y = rw.v.x + rw.v.y + rw.v.z;
    h.z = rw.v.y + rw.v.z + rw.v.w;
    h.w = rw.v.z + rw.v.w + r;
    return h;
}

__device__ __forceinline__ float4 stencil_out(const float4& a, const float4& b,
                                              const float4& c, const float4& v) {
    float4 o;
    o.x = fabsf(0.125f * (a.x + b.x + c.x) - 1.125f * v.x) + 1e-5f;
    o.y = fabsf(0.125f * (a.y + b.y + c.y) - 1.125f * v.y) + 1e-5f;
    o.z = fabsf(0.125f * (a.z + b.z + c.z) - 1.125f * v.z) + 1e-5f;
    o.w = fabsf(0.125f * (a.w + b.w + c.w) - 1.125f * v.w) + 1e-5f;
    return o;
}

// ================= interior: strips 1..14, prefetch depth 3 =================
// Per plane: 56 warp-strips (14 row-strips x 4 col-strips) -> 7 CTAs of 8 warps.
__global__ __launch_bounds__(256, 5)
void highpass_interior(const float* __restrict__ x, float* __restrict__ y) {
    const int warp = threadIdx.x >> 5;
    const int lane = threadIdx.x & 31;

    const int sid   = blockIdx.x * 8 + warp;        // 0..55
    const int c0    = (sid & 3) * TW;
    const int rbase = (1 + (sid >> 2)) * ROWS;      // strips 1..14
    const int col   = c0 + lane * 4;

    const float* __restrict__ xp = x + ((size_t)blockIdx.y << 18);
    float* __restrict__ yp       = y + ((size_t)blockIdx.y << 18);

    // prime: rows rbase-1 .. rbase+3 (all in-range for interior strips)
    Row rm = load_row_u(xp, rbase - 1, c0, col, lane);
    Row rc = load_row_u(xp, rbase,     c0, col, lane);
    Row r1 = load_row_u(xp, rbase + 1, c0, col, lane);
    Row r2 = load_row_u(xp, rbase + 2, c0, col, lane);
    Row r3 = load_row_u(xp, rbase + 3, c0, col, lane);

    float4 hsA = hsum(rm, lane);
    float4 hsB = hsum(rc, lane);
    float4 vc  = rc.v;

    float* op = yp + rbase * W + col;

    #pragma unroll 4
    for (int i = 0; i < ROWS; i++) {
        Row r4 = load_row_u(xp, rbase + i + 4, c0, col, lane);  // prefetch d=3
        float4 hsC = hsum(r1, lane);

        float4 o = stencil_out(hsA, hsB, hsC, vc);
        __stcs(reinterpret_cast<float4*>(op), o);
        op += W;

        hsA = hsB; hsB = hsC; vc = r1.v;
        r1 = r2; r2 = r3; r3 = r4;
    }
}

// Note: interior prefetch reads up to row rbase+ROWS+3 = rbase+35 <= 483 (strip 14)
// and down to rbase-1 >= 31 (strip 1): always in-range, loads unguarded.

// ================= boundary: strips 0 and 15, guarded, depth 2 ==============
// One CTA per plane: 8 warps = 2 row-strips x 4 col-strips.
__global__ __launch_bounds__(256, 5)
void highpass_boundary(const float* __restrict__ x, float* __restrict__ y) {
    const int warp = threadIdx.x >> 5;
    const int lane = threadIdx.x & 31;

    const int c0    = (warp & 3) * TW;
    const int rbase = (warp >> 2) ? (H - ROWS) : 0;   // strip 15 or strip 0
    const int col   = c0 + lane * 4;

    const float* __restrict__ xp = x + ((size_t)blockIdx.x << 18);
    float* __restrict__ yp       = y + ((size_t)blockIdx.x << 18);

    Row rm = load_row_g(xp, rbase - 1, c0, col, lane);
    Row rc = load_row_g(xp, rbase,     c0, col, lane);
    Row r1 = load_row_g(xp, rbase + 1, c0, col, lane);
    Row r2 = load_row_g(xp, rbase + 2, c0, col, lane);

    float4 hsA = hsum(rm, lane);
    float4 hsB = hsum(rc, lane);
    float4 vc  = rc.v;

    float* op = yp + rbase * W + col;

    #pragma unroll 4
    for (int i = 0; i < ROWS; i++) {
        Row r3 = load_row_g(xp, rbase + i + 3, c0, col, lane);  // prefetch d=2
        float4 hsC = hsum(r1, lane);

        float4 o = stencil_out(hsA, hsB, hsC, vc);
        __stcs(reinterpret_cast<float4*>(op), o);
        op += W;

        hsA = hsB; hsB = hsC; vc = r1.v;
        r1 = r2; r2 = r3;
    }
}

extern "C" void kernel_launch(void* const* d_in, const int* in_sizes, int n_in,
                              void* d_out, int out_size) {
    const float* x = (const float*)d_in[0];
    float* y = (float*)d_out;

    const int planes = out_size / (W * H);   // 256

    dim3 block(256, 1, 1);
    dim3 grid_i(7, planes, 1);               // 7 CTAs/plane (strips 1..14)
    highpass_interior<<<grid_i, block>>>(x, y);

    dim3 grid_b(planes, 1, 1);               // 1 CTA/plane (strips 0, 15)
    highpass_boundary<<<grid_b, block>>>(x, y);
}

// round 12
// speedup vs baseline: 1.1304x; 1.1304x over previous
#include <cuda_runtime.h>
#include <cuda_bf16.h>

// 3x3 high-pass stencil: y = |0.125*(hs_top+hs_mid+hs_bot) - 1.125*center| + 1e-5
// x: (8,32,512,512) fp32, zero-padded SAME. Register-rolling, smem-free.
// Single launch; warp-uniform fast path (unguarded loads) for interior strips,
// guarded path for the top/bottom strips. 128-thr CTAs for fine tail granularity.

#define W 512
#define H 512
#define ROWS 32
#define TW 128
#define WARPS 4   // warps per CTA

struct Row {
    float4 v;   // lane's 4 columns
    float  e;   // strip-edge neighbor: left on lane 0, right on lane 31
};

// guarded (handles rr outside [0,H) with zero-fill) — boundary strips only
__device__ __forceinline__ Row load_row_g(const float* __restrict__ xp, int rr,
                                          int c0, int col, int lane) {
    Row o;
    o.e = 0.f;
    if ((unsigned)rr < H) {
        o.v = *reinterpret_cast<const float4*>(xp + rr * W + col);
        if (lane == 0) {
            if (c0 > 0) o.e = xp[rr * W + (c0 - 1)];
        } else if (lane == 31) {
            if (c0 + TW < W) o.e = xp[rr * W + (c0 + TW)];
        }
    } else {
        o.v = make_float4(0.f, 0.f, 0.f, 0.f);
    }
    return o;
}

// unguarded — interior strips, rr always in range
__device__ __forceinline__ Row load_row_u(const float* __restrict__ xp, int rr,
                                          int c0, int col, int lane) {
    Row o;
    o.e = 0.f;
    o.v = *reinterpret_cast<const float4*>(xp + rr * W + col);
    if (lane == 0) {
        if (c0 > 0) o.e = xp[rr * W + (c0 - 1)];
    } else if (lane == 31) {
        if (c0 + TW < W) o.e = xp[rr * W + (c0 + TW)];
    }
    return o;
}

__device__ __forceinline__ float4 hsum(const Row& rw, int lane) {
    float l = __shfl_up_sync(0xffffffffu, rw.v.w, 1);
    if (lane == 0) l = rw.e;
    float r = __shfl_down_sync(0xffffffffu, rw.v.x, 1);
    if (lane == 31) r = rw.e;
    float4 h;
    h.x = l      + rw.v.x + rw.v.y;
    h.y = rw.v.x + rw.v.y + rw.v.z;
    h.z = rw.v.y + rw.v.z + rw.v.w;
    h.w = rw.v.z + rw.v.w + r;
    return h;
}

__device__ __forceinline__ float4 stencil_out(const float4& a, const float4& b,
                                              const float4& c, const float4& v) {
    float4 o;
    o.x = fabsf(0.125f * (a.x + b.x + c.x) - 1.125f * v.x) + 1e-5f;
    o.y = fabsf(0.125f * (a.y + b.y + c.y) - 1.125f * v.y) + 1e-5f;
    o.z = fabsf(0.125f * (a.z + b.z + c.z) - 1.125f * v.z) + 1e-5f;
    o.w = fabsf(0.125f * (a.w + b.w + c.w) - 1.125f * v.w) + 1e-5f;
    return o;
}

__global__ __launch_bounds__(128, 10)
void highpass_kernel(const float* __restrict__ x, float* __restrict__ y) {
    const int warp = threadIdx.x >> 5;
    const int lane = threadIdx.x & 31;

    const int c0    = blockIdx.x * TW;
    const int rbase = (blockIdx.y * WARPS + warp) * ROWS;
    const int col   = c0 + lane * 4;

    const float* __restrict__ xp = x + ((size_t)blockIdx.z << 18);
    float* __restrict__ yp       = y + ((size_t)blockIdx.z << 18);

    float* op = yp + rbase * W + col;

    if (rbase > 0 && rbase < H - ROWS) {
        // ---------- interior: unguarded loads (rows rbase-1 .. rbase+ROWS+2 in range) ----------
        Row rm  = load_row_u(xp, rbase - 1, c0, col, lane);
        Row rc  = load_row_u(xp, rbase,     c0, col, lane);
        Row r1  = load_row_u(xp, rbase + 1, c0, col, lane);
        Row r2  = load_row_u(xp, rbase + 2, c0, col, lane);

        float4 hsA = hsum(rm, lane);
        float4 hsB = hsum(rc, lane);
        float4 vc  = rc.v;

        #pragma unroll 4
        for (int i = 0; i < ROWS; i++) {
            Row r3 = load_row_u(xp, rbase + i + 3, c0, col, lane);  // prefetch d=2
            float4 hsC = hsum(r1, lane);

            float4 o = stencil_out(hsA, hsB, hsC, vc);
            __stcs(reinterpret_cast<float4*>(op), o);
            op += W;

            hsA = hsB; hsB = hsC; vc = r1.v;
            r1 = r2; r2 = r3;
        }
    } else {
        // ---------- boundary strips (rbase == 0 or H-ROWS): guarded ----------
        Row rm  = load_row_g(xp, rbase - 1, c0, col, lane);
        Row rc  = load_row_g(xp, rbase,     c0, col, lane);
        Row r1  = load_row_g(xp, rbase + 1, c0, col, lane);
        Row r2  = load_row_g(xp, rbase + 2, c0, col, lane);

        float4 hsA = hsum(rm, lane);
        float4 hsB = hsum(rc, lane);
        float4 vc  = rc.v;

        #pragma unroll 4
        for (int i = 0; i < ROWS; i++) {
            Row r3 = load_row_g(xp, rbase + i + 3, c0, col, lane);  // prefetch d=2
            float4 hsC = hsum(r1, lane);

            float4 o = stencil_out(hsA, hsB, hsC, vc);
            __stcs(reinterpret_cast<float4*>(op), o);
            op += W;

            hsA = hsB; hsB = hsC; vc = r1.v;
            r1 = r2; r2 = r3;
        }
    }
}

extern "C" void kernel_launch(void* const* d_in, const int* in_sizes, int n_in,
                              void* d_out, int out_size) {
    const float* x = (const float*)d_in[0];
    float* y = (float*)d_out;

    const int planes = out_size / (W * H);               // 256
    dim3 block(128, 1, 1);                               // 4 warps
    dim3 grid(W / TW, H / (ROWS * WARPS), planes);       // (4, 4, 256) = 4096 CTAs
    highpass_kernel<<<grid, block>>>(x, y);
}

// round 13
// speedup vs baseline: 1.1809x; 1.0447x over previous
#include <cuda_runtime.h>
#include <cuda_bf16.h>

// 3x3 high-pass stencil: y = |0.125*(hs_top+hs_mid+hs_bot) - 1.125*center| + 1e-5
// x: (8,32,512,512) fp32, zero-padded SAME. Register-rolling, smem-free.
// Warp strip: 128 cols x 32 rows, prefetch d=2, L2-only loads (__ldcg),
// streaming stores, unroll 8 for deep load batching.

#define W 512
#define H 512
#define ROWS 32
#define WARPS 8
#define TW 128

struct Row {
    float4 v;   // lane's 4 columns
    float  e;   // strip-edge neighbor: left on lane 0, right on lane 31
};

__device__ __forceinline__ Row load_row(const float* __restrict__ xp, int rr,
                                        int c0, int col, int lane) {
    Row o;
    o.e = 0.f;
    if ((unsigned)rr < H) {
        o.v = __ldcg(reinterpret_cast<const float4*>(xp + rr * W + col));
        if (lane == 0) {
            if (c0 > 0) o.e = __ldcg(xp + rr * W + (c0 - 1));
        } else if (lane == 31) {
            if (c0 + TW < W) o.e = __ldcg(xp + rr * W + (c0 + TW));
        }
    } else {
        o.v = make_float4(0.f, 0.f, 0.f, 0.f);
    }
    return o;
}

__device__ __forceinline__ float4 hsum(const Row& rw, int lane) {
    float l = __shfl_up_sync(0xffffffffu, rw.v.w, 1);
    if (lane == 0) l = rw.e;
    float r = __shfl_down_sync(0xffffffffu, rw.v.x, 1);
    if (lane == 31) r = rw.e;
    float4 h;
    h.x = l      + rw.v.x + rw.v.y;
    h.y = rw.v.x + rw.v.y + rw.v.z;
    h.z = rw.v.y + rw.v.z + rw.v.w;
    h.w = rw.v.z + rw.v.w + r;
    return h;
}

__global__ __launch_bounds__(256, 5)
void highpass_kernel(const float* __restrict__ x, float* __restrict__ y) {
    const int warp = threadIdx.x >> 5;
    const int lane = threadIdx.x & 31;

    const int c0    = blockIdx.x * TW;
    const int rbase = (blockIdx.y * WARPS + warp) * ROWS;
    const int col   = c0 + lane * 4;

    const float* __restrict__ xp = x + ((size_t)blockIdx.z << 18);
    float* __restrict__ yp       = y + ((size_t)blockIdx.z << 18);

    // prime the pipeline: rows rbase-1 .. rbase+2
    Row rm  = load_row(xp, rbase - 1, c0, col, lane);
    Row rc  = load_row(xp, rbase,     c0, col, lane);
    Row rn  = load_row(xp, rbase + 1, c0, col, lane);
    Row rn2 = load_row(xp, rbase + 2, c0, col, lane);

    float4 hsA = hsum(rm, lane);
    float4 hsB = hsum(rc, lane);
    float4 vc  = rc.v;

    float* op = yp + rbase * W + col;

    #pragma unroll 8
    for (int i = 0; i < ROWS; i++) {
        Row rn3 = load_row(xp, rbase + i + 3, c0, col, lane);  // prefetch d=2
        float4 hsC = hsum(rn, lane);

        float4 o;
        o.x = fabsf(0.125f * (hsA.x + hsB.x + hsC.x) - 1.125f * vc.x) + 1e-5f;
        o.y = fabsf(0.125f * (hsA.y + hsB.y + hsC.y) - 1.125f * vc.y) + 1e-5f;
        o.z = fabsf(0.125f * (hsA.z + hsB.z + hsC.z) - 1.125f * vc.z) + 1e-5f;
        o.w = fabsf(0.125f * (hsA.w + hsB.w + hsC.w) - 1.125f * vc.w) + 1e-5f;

        __stcs(reinterpret_cast<float4*>(op), o);   // streaming store: no reuse
        op += W;

        hsA = hsB; hsB = hsC; vc = rn.v; rn = rn2; rn2 = rn3;
    }
}

extern "C" void kernel_launch(void* const* d_in, const int* in_sizes, int n_in,
                              void* d_out, int out_size) {
    const float* x = (const float*)d_in[0];
    float* y = (float*)d_out;

    const int planes = out_size / (W * H);           // 256
    dim3 block(256, 1, 1);                           // 8 warps
    dim3 grid(W / TW, H / (ROWS * WARPS), planes);   // (4, 2, 256) = 2048 CTAs
    highpass_kernel<<<grid, block>>>(x, y);
}

// round 14
// speedup vs baseline: 1.2088x; 1.0236x over previous
#include <cuda_runtime.h>
#include <cuda_bf16.h>

// 3x3 high-pass stencil: y = |0.125*(hs_top+hs_mid+hs_bot) - 1.125*center| + 1e-5
// x: (8,32,512,512) fp32, zero-padded SAME. Register-rolling, smem-free.
// Warp strip: 128 cols x 32 rows, prefetch d=2, __ldcg loads, __stcs stores,
// fully unrolled main loop, rolling pointers, hoisted edge pointer.

#define W 512
#define H 512
#define ROWS 32
#define WARPS 8
#define TW 128

struct Row {
    float4 v;   // lane's 4 columns
    float  e;   // strip-edge neighbor: left on lane 0, right on lane 31
};

// rp: pointer to this lane's vec4 in row rr; ep: edge pointer (or null); rr for guard
__device__ __forceinline__ Row load_row(const float* rp, const float* ep, int rr) {
    Row o;
    o.e = 0.f;
    if ((unsigned)rr < H) {
        o.v = __ldcg(reinterpret_cast<const float4*>(rp));
        if (ep) o.e = __ldcg(ep);
    } else {
        o.v = make_float4(0.f, 0.f, 0.f, 0.f);
    }
    return o;
}

__device__ __forceinline__ float4 hsum(const Row& rw, int lane) {
    float l = __shfl_up_sync(0xffffffffu, rw.v.w, 1);
    if (lane == 0) l = rw.e;
    float r = __shfl_down_sync(0xffffffffu, rw.v.x, 1);
    if (lane == 31) r = rw.e;
    float4 h;
    h.x = l      + rw.v.x + rw.v.y;
    h.y = rw.v.x + rw.v.y + rw.v.z;
    h.z = rw.v.y + rw.v.z + rw.v.w;
    h.w = rw.v.z + rw.v.w + r;
    return h;
}

__global__ __launch_bounds__(256, 5)
void highpass_kernel(const float* __restrict__ x, float* __restrict__ y) {
    const int warp = threadIdx.x >> 5;
    const int lane = threadIdx.x & 31;

    const int c0    = blockIdx.x * TW;
    const int rbase = (blockIdx.y * WARPS + warp) * ROWS;
    const int col   = c0 + lane * 4;

    const float* __restrict__ xp = x + ((size_t)blockIdx.z << 18);
    float* __restrict__ yp       = y + ((size_t)blockIdx.z << 18);

    // rolling pointers (start at row rbase-1)
    const float* rp = xp + (rbase - 1) * W + col;

    // hoisted edge pointer: lane 0 -> left halo col, lane 31 -> right halo col
    const float* ep = nullptr;
    if (lane == 0) {
        if (c0 > 0) ep = xp + (rbase - 1) * W + (c0 - 1);
    } else if (lane == 31) {
        if (c0 + TW < W) ep = xp + (rbase - 1) * W + (c0 + TW);
    }
    const int epinc = ep ? W : 0;

    // prime the pipeline: rows rbase-1 .. rbase+2
    Row rm  = load_row(rp, ep, rbase - 1);  rp += W; ep += epinc;
    Row rc  = load_row(rp, ep, rbase);      rp += W; ep += epinc;
    Row rn  = load_row(rp, ep, rbase + 1);  rp += W; ep += epinc;
    Row rn2 = load_row(rp, ep, rbase + 2);  rp += W; ep += epinc;

    float4 hsA = hsum(rm, lane);
    float4 hsB = hsum(rc, lane);
    float4 vc  = rc.v;

    float* op = yp + rbase * W + col;

    #pragma unroll
    for (int i = 0; i < ROWS; i++) {
        Row rn3 = load_row(rp, ep, rbase + i + 3);  // prefetch d=2
        rp += W; ep += epinc;

        float4 hsC = hsum(rn, lane);

        float4 o;
        o.x = fabsf(0.125f * (hsA.x + hsB.x + hsC.x) - 1.125f * vc.x) + 1e-5f;
        o.y = fabsf(0.125f * (hsA.y + hsB.y + hsC.y) - 1.125f * vc.y) + 1e-5f;
        o.z = fabsf(0.125f * (hsA.z + hsB.z + hsC.z) - 1.125f * vc.z) + 1e-5f;
        o.w = fabsf(0.125f * (hsA.w + hsB.w + hsC.w) - 1.125f * vc.w) + 1e-5f;

        __stcs(reinterpret_cast<float4*>(op), o);   // streaming store
        op += W;

        hsA = hsB; hsB = hsC; vc = rn.v; rn = rn2; rn2 = rn3;
    }
}

extern "C" void kernel_launch(void* const* d_in, const int* in_sizes, int n_in,
                              void* d_out, int out_size) {
    const float* x = (const float*)d_in[0];
    float* y = (float*)d_out;

    const int planes = out_size / (W * H);           // 256
    dim3 block(256, 1, 1);                           // 8 warps
    dim3 grid(W / TW, H / (ROWS * WARPS), planes);   // (4, 2, 256) = 2048 CTAs
    highpass_kernel<<<grid, block>>>(x, y);
}